// round 8
// baseline (speedup 1.0000x reference)
#include <cuda_runtime.h>

// ---------------------------------------------------------------------------
// R8: 8 rows per warp — amortize the dependent-load latency chain and
// de-duplicate the warp-uniform ladder.
//
// R7 post-mortem: duration was invariant to instruction count (6.1us across
// R5/R6/R7) => the kernel is floored by per-warp exposure of the 2-deep
// dependent load chain (addr -> gather) at 1 row/warp, with every lane
// redundantly computing the same row's ladder.
//
// New structure: lanes 0..7 each OWN a row (warp covers 8 rows):
//  * coalesced addr/outp loads, gather issued as ONE divergent LDG (MLP=8),
//  * integer digit ladder / count / nibble-pack computed per-lane (8 rows of
//    ladder work in one SIMD pass),
//  * rare paths (qmax cutoff bands, v<1001 soft pos-0 sum) per-lane serial,
//    predicated (~1% of lanes),
//  * epilogue: 8x { 3 shfls broadcast (pack|n<<24, op, v) from lane r,
//    branch-free token compute, 2 coalesced 128B stores + lane0 value col }.
//
// Digit semantics identical to R6/R7 (passed, rel_err 3.3e-6):
//  * value = |mem[b, addr[b]]| exactly (eq_gate is an exact one-hot);
//  * floor(v/10^p) == integer /10 ladder on u=(int)v (v < 2^24);
//  * qmax clipping {999,101,11,2,1,1} (reference loop break);
//  * cutoff bands: quot = qmax*st near v = (qmax+1)*d - 0.5;
//  * pos 0 soft 4-term ascending sum when v < 1001.
// ---------------------------------------------------------------------------

static __device__ __forceinline__ float sigm(float z) {
    return __fdividef(1.0f, 1.0f + __expf(-z));
}
// silu_threshold(x) = (silu(20x+10) - silu(20x-10)) / 20
static __device__ __forceinline__ float st_fast(float x) {
    float z1 = __fmaf_rn(20.0f, x, 10.0f);
    float z2 = __fmaf_rn(20.0f, x, -10.0f);
    return (z1 * sigm(z1) - z2 * sigm(z2)) * 0.05f;
}
// reference digit = floor(quot - floor(quot/10)*10); handles negative quot.
static __device__ __forceinline__ int mod10_digit(float quot) {
    return (int)floorf(quot - floorf(quot * 0.1f) * 10.0f);
}

__global__ void __launch_bounds__(128)
c4_printf_mr_kernel(const float* __restrict__ mem,
                    const int*   __restrict__ addr,
                    const int*   __restrict__ outp,
                    float*       __restrict__ out,
                    int B, int M) {
    const unsigned FULL = 0xFFFFFFFFu;
    int lane = threadIdx.x & 31;
    int warp = (blockIdx.x * blockDim.x + threadIdx.x) >> 5;
    int base = warp * 8;                 // this warp covers rows base..base+7
    if (base >= B) return;

    // --- owner phase: lanes 0..7 each own one row -----------------------------
    int   myrow = base + lane;
    bool  owner = (lane < 8) && (myrow < B);

    float v  = 0.0f;
    int   op = 0;
    unsigned pkn = 0;                    // digits nibble-packed | (n << 24)

    if (owner) {
        int a = __ldg(addr + myrow);     // coalesced across lanes 0..7
        op    = __ldg(outp + myrow);
        v     = fabsf(__ldg(mem + myrow * M + a));   // MLP=8 in one LDG

        // integer digit ladder (exact: u = floor(v), v < 2^24)
        int u  = (int)v;
        int q1 = u  / 10;
        int q2 = q1 / 10;
        int q3 = q2 / 10;
        int q4 = q3 / 10;
        int q5 = q4 / 10;
        int q6 = q5 / 10;
        int d1 = (q1 <= 101) ? (q1 - 10 * q2) : 0;
        int d2 = (q2 <= 11)  ? (q2 - 10 * q3) : 0;
        int d3 = (q3 <= 2)   ? (q3 - 10 * q4) : 0;
        int d4 = (q4 <= 1)   ? (q4 - 10 * q5) : 0;
        int d5 = (q5 <= 1)   ? (q5 - 10 * q6) : 0;

        int n = 1 + (u >= 10) + (u >= 100) + (u >= 1000)
                  + (u >= 10000) + (u >= 100000);

        // qmax cutoff bands (~0.03% of lanes)
        if (v > 1018.0f && v < 20001.0f) {
            if (fabsf(v - 1019.5f) < 1.41f) {
                float g = 1019.5f - v;
                float s = (g > -1.4011f) ? st_fast(g) : 0.0f;
                d1 = mod10_digit(101.0f * s);
            } else if (fabsf(v - 1199.5f) < 1.41f) {
                float g = 1199.5f - v;
                float s = (g > -1.4011f) ? st_fast(g) : 0.0f;
                d2 = mod10_digit(11.0f * s);
            } else if (fabsf(v - 2999.5f) < 1.41f) {
                float g = 2999.5f - v;
                float s = (g > -1.4011f) ? st_fast(g) : 0.0f;
                d3 = mod10_digit(2.0f * s);
            } else if (fabsf(v - 19999.5f) < 1.41f) {
                float g = 19999.5f - v;
                float s = (g > -1.4011f) ? st_fast(g) : 0.0f;
                d4 = mod10_digit(1.0f * s);
            }
        }

        // pos 0: soft 4-term ascending sum (per-lane serial; ~1% of lanes)
        int d0 = 0;
        if (v < 1001.0f) {
            int qlo = (int)floorf(v - 1.93f) + 1;
            float quot = 0.0f;
            #pragma unroll
            for (int k = 0; k < 4; ++k) {
                int q = qlo + k;
                if (q >= 0 && q <= 999) {
                    float qf = (float)q;
                    float a1 = v - qf + 0.5f;        // lower gate arg (d = 1)
                    float a2 = qf + 0.5f - v;        // upper gate arg
                    quot += st_fast(a1) * st_fast(a2) * qf;
                }
            }
            d0 = mod10_digit(quot);
        }

        pkn = (unsigned)d0 | ((unsigned)d1 << 4) | ((unsigned)d2 << 8)
            | ((unsigned)d3 << 12) | ((unsigned)d4 << 16)
            | ((unsigned)d5 << 20) | ((unsigned)n << 24);
    }

    // --- epilogue: 8 rows, 2 coalesced 128B stores each ------------------------
    #pragma unroll
    for (int r = 0; r < 8; ++r) {
        int row = base + r;
        if (row >= B) break;
        unsigned pk = __shfl_sync(FULL, pkn, r);
        int      o  = __shfl_sync(FULL, op,  r);
        float    vv = __shfl_sync(FULL, v,   r);
        int nn = (int)(pk >> 24);

        int j0 = lane - o;
        int j1 = j0 + 32;
        int pi0 = nn - 1 - j0; pi0 = pi0 < 0 ? 0 : (pi0 > 5 ? 5 : pi0);
        int pi1 = nn - 1 - j1; pi1 = pi1 < 0 ? 0 : (pi1 > 5 ? 5 : pi1);
        float g0 = (float)((pk >> (pi0 * 4)) & 15u);
        float g1 = (float)((pk >> (pi1 * 4)) & 15u);

        float t0 = (j0 >= 0 && j0 < nn) ? (48.0f + g0)
                                        : ((j0 == nn) ? 10.0f : 0.0f);
        float t1 = (j1 >= 0 && j1 < nn) ? (48.0f + g1)
                                        : ((j1 == nn) ? 10.0f : 0.0f);

        float* orow = out + row * 65;
        orow[lane]      = t0;
        orow[lane + 32] = t1;
        if (lane == 0) orow[64] = vv;    // appended value column (exact)
    }
}

extern "C" void kernel_launch(void* const* d_in, const int* in_sizes, int n_in,
                              void* d_out, int out_size) {
    const float* mem  = (const float*)d_in[0];   // [B, M] fp32
    const int*   addr = (const int*)d_in[1];     // [B] int32
    const int*   outp = (const int*)d_in[2];     // [B] int32
    float*       out  = (float*)d_out;           // [B, 65] fp32

    int B = in_sizes[1];
    int M = in_sizes[0] / B;

    // 8 rows per warp, 4 warps per block -> 32 rows per block.
    int rows_per_block = 32;
    int blocks = (B + rows_per_block - 1) / rows_per_block;   // 256 for B=8192
    c4_printf_mr_kernel<<<blocks, 128>>>(mem, addr, outp, out, B, M);
}

// round 9
// speedup vs baseline: 1.1442x; 1.1442x over previous
#include <cuda_runtime.h>

// ---------------------------------------------------------------------------
// R9: best-measured shape (R6: warp-per-row, 256-thr blocks) + best-measured
// math (R7: integer digit ladder), minimal warp path.
//
// Floor analysis (R6-R8): kernel time is pinned at ~6.1-6.5us across 3
// structural variants spanning 8x instruction-count and 6x occupancy ranges.
// DRAM traffic == gather sectors only (~1MB); stores are L2-absorbed.
// => duration = fixed launch/ramp/tail overhead + one exposed addr->gather
// DRAM chain. This round removes residual slack and restores the best
// harness configuration; no structural lever remains below that floor.
//
// Reference semantics (verified R2-R8, rel_err 3.3e-6):
//  * value = |mem[b, addr[b]]| exactly (eq_gate is an exact one-hot).
//  * floor(v/10^p) == integer /10 ladder on u = (int)v  (v < 2^24).
//  * digit count n = 1 + #{i in 1..5 : u >= 10^i}.
//  * qmax clipping per pos {999,101,11,2,1,1} (reference loop break).
//  * cutoff bands (quot = qmax*st near v = (qmax+1)*d - 0.5): soft fallback.
//  * pos 0 soft 4-term ascending sum when v < 1001: soft fallback.
// ---------------------------------------------------------------------------

static __device__ __forceinline__ float sigm(float z) {
    return __fdividef(1.0f, 1.0f + __expf(-z));
}
// silu_threshold(x) = (silu(20x+10) - silu(20x-10)) / 20
static __device__ __forceinline__ float st_fast(float x) {
    float z1 = __fmaf_rn(20.0f, x, 10.0f);
    float z2 = __fmaf_rn(20.0f, x, -10.0f);
    return (z1 * sigm(z1) - z2 * sigm(z2)) * 0.05f;
}
// reference digit = floor(quot - floor(quot/10)*10); handles negative quot.
static __device__ __forceinline__ int mod10_digit(float quot) {
    return (int)floorf(quot - floorf(quot * 0.1f) * 10.0f);
}

__global__ void __launch_bounds__(256)
c4_printf_warp_kernel(const float* __restrict__ mem,
                      const int*   __restrict__ addr,
                      const int*   __restrict__ outp,
                      float*       __restrict__ out,
                      int B, int M) {
    int warp = (blockIdx.x * blockDim.x + threadIdx.x) >> 5;
    int lane = threadIdx.x & 31;
    if (warp >= B) return;
    const int b = warp;

    // Warp-uniform loads (one sector each, L1 broadcast). The addr->gather
    // dependency is the kernel's single exposed latency chain.
    int   a  = __ldg(addr + b);
    int   op = __ldg(outp + b);
    float v  = fabsf(__ldg(mem + b * M + a));

    // --- integer digit ladder (exact) -----------------------------------------
    int u  = (int)v;                 // exact floor, v < 2^24
    int q1 = u  / 10;
    int q2 = q1 / 10;
    int q3 = q2 / 10;
    int q4 = q3 / 10;
    int q5 = q4 / 10;
    int q6 = q5 / 10;
    int d1 = (q1 <= 101) ? (q1 - 10 * q2) : 0;
    int d2 = (q2 <= 11)  ? (q2 - 10 * q3) : 0;
    int d3 = (q3 <= 2)   ? (q3 - 10 * q4) : 0;
    int d4 = (q4 <= 1)   ? (q4 - 10 * q5) : 0;
    int d5 = (q5 <= 1)   ? (q5 - 10 * q6) : 0;

    int n = 1 + (u >= 10) + (u >= 100) + (u >= 1000)
              + (u >= 10000) + (u >= 100000);

    // --- qmax cutoff bands (warp-uniform branch, ~0.03% taken) ----------------
    if (v > 1018.0f && v < 20001.0f) {
        if (fabsf(v - 1019.5f) < 1.41f) {
            float g = 1019.5f - v;
            float s = (g > -1.4011f) ? st_fast(g) : 0.0f;
            d1 = mod10_digit(101.0f * s);
        } else if (fabsf(v - 1199.5f) < 1.41f) {
            float g = 1199.5f - v;
            float s = (g > -1.4011f) ? st_fast(g) : 0.0f;
            d2 = mod10_digit(11.0f * s);
        } else if (fabsf(v - 2999.5f) < 1.41f) {
            float g = 2999.5f - v;
            float s = (g > -1.4011f) ? st_fast(g) : 0.0f;
            d3 = mod10_digit(2.0f * s);
        } else if (fabsf(v - 19999.5f) < 1.41f) {
            float g = 19999.5f - v;
            float s = (g > -1.4011f) ? st_fast(g) : 0.0f;
            d4 = mod10_digit(1.0f * s);
        }
    }

    // --- pos 0: soft 4-term ascending sum (warp-uniform, ~1% taken) -----------
    int d0 = 0;
    if (v < 1001.0f) {
        const unsigned FULL = 0xFFFFFFFFu;
        int off = lane & 3;                        // each 4-lane group computes
        int qlo = (int)floorf(v - 1.93f) + 1;      // the same 4 live terms
        int q = qlo + off;
        float term = 0.0f;
        if (q >= 0 && q <= 999) {
            float qf = (float)q;
            float a1 = v - qf + 0.5f;              // lower gate arg (d = 1)
            float a2 = qf + 0.5f - v;              // upper gate arg
            term = st_fast(a1) * st_fast(a2) * qf;
        }
        term += __shfl_xor_sync(FULL, term, 1);    // group-of-4 reduction
        term += __shfl_xor_sync(FULL, term, 2);
        d0 = mod10_digit(term);
    }

    // --- nibble-pack digits (warp-uniform) -------------------------------------
    unsigned pack = (unsigned)d0 | ((unsigned)d1 << 4) | ((unsigned)d2 << 8)
                  | ((unsigned)d3 << 12) | ((unsigned)d4 << 16)
                  | ((unsigned)d5 << 20);

    // --- branch-free epilogue: lane owns cols lane and lane+32 ------------------
    float* orow = out + b * 65;
    int j0 = lane - op;
    int j1 = j0 + 32;

    int pi0 = n - 1 - j0; pi0 = pi0 < 0 ? 0 : (pi0 > 5 ? 5 : pi0);
    int pi1 = n - 1 - j1; pi1 = pi1 < 0 ? 0 : (pi1 > 5 ? 5 : pi1);
    float g0 = (float)((pack >> (pi0 * 4)) & 15u);
    float g1 = (float)((pack >> (pi1 * 4)) & 15u);

    float t0 = (j0 >= 0 && j0 < n) ? (48.0f + g0) : ((j0 == n) ? 10.0f : 0.0f);
    float t1 = (j1 >= 0 && j1 < n) ? (48.0f + g1) : ((j1 == n) ? 10.0f : 0.0f);

    orow[lane]      = t0;       // two coalesced 128B stores per row
    orow[lane + 32] = t1;
    if (lane == 0) orow[64] = v; // appended value column (exact)
}

extern "C" void kernel_launch(void* const* d_in, const int* in_sizes, int n_in,
                              void* d_out, int out_size) {
    const float* mem  = (const float*)d_in[0];   // [B, M] fp32
    const int*   addr = (const int*)d_in[1];     // [B] int32
    const int*   outp = (const int*)d_in[2];     // [B] int32
    float*       out  = (float*)d_out;           // [B, 65] fp32

    int B = in_sizes[1];
    int M = in_sizes[0] / B;

    // Best-measured config (R6): warp-per-row, 8 warps/block, 1024 blocks.
    int threads = 256;
    int blocks  = (B + (threads / 32) - 1) / (threads / 32);
    c4_printf_warp_kernel<<<blocks, threads>>>(mem, addr, outp, out, B, M);
}

// round 10
// speedup vs baseline: 1.1827x; 1.0337x over previous
#include <cuda_runtime.h>

// ---------------------------------------------------------------------------
// R10: best-measured config (warp-per-row, 256-thr blocks, integer ladder)
// with hot-path instruction squeeze.
//
// Floor analysis (R6-R9): duration ~6.1-6.5us kernel across 4 structural
// variants. Back-solving issue%/inst-count shows the chip runs at a
// low (un-boosted) clock for this micro-kernel; elapsed cycles decompose as
// launch/ramp + one exposed addr->gather DRAM chain + ~1.6k issue cycles.
// Only the issue term is compressible: this round cuts it via
//   * unsigned /10 ladder (cheaper IMAD.HI sequence x6),
//   * digit count derived from ladder quotients (q_p > 0 <=> u >= 10^p),
//     deleting 5 large-constant compares,
//   * nibble-pack + branch-free epilogue unchanged from best config.
//
// Reference semantics (verified R2-R9, rel_err 3.279e-6):
//  * value = |mem[b, addr[b]]| exactly (eq_gate is an exact one-hot).
//  * floor(v/10^p) == unsigned /10 ladder on u = (unsigned)v  (v < 2^24).
//  * n = 1 + #{p in 1..5 : u >= 10^p} = 1 + #{p : q_p != 0}.
//  * qmax clipping per pos {999,101,11,2,1,1} (reference loop break).
//  * cutoff bands (quot = qmax*st near v = (qmax+1)*d - 0.5): soft fallback.
//  * pos 0 soft 4-term ascending sum when v < 1001: soft fallback.
// ---------------------------------------------------------------------------

static __device__ __forceinline__ float sigm(float z) {
    return __fdividef(1.0f, 1.0f + __expf(-z));
}
// silu_threshold(x) = (silu(20x+10) - silu(20x-10)) / 20
static __device__ __forceinline__ float st_fast(float x) {
    float z1 = __fmaf_rn(20.0f, x, 10.0f);
    float z2 = __fmaf_rn(20.0f, x, -10.0f);
    return (z1 * sigm(z1) - z2 * sigm(z2)) * 0.05f;
}
// reference digit = floor(quot - floor(quot/10)*10); handles negative quot.
static __device__ __forceinline__ int mod10_digit(float quot) {
    return (int)floorf(quot - floorf(quot * 0.1f) * 10.0f);
}

__global__ void __launch_bounds__(256)
c4_printf_warp_kernel(const float* __restrict__ mem,
                      const int*   __restrict__ addr,
                      const int*   __restrict__ outp,
                      float*       __restrict__ out,
                      int B, int M) {
    int warp = (blockIdx.x * blockDim.x + threadIdx.x) >> 5;
    int lane = threadIdx.x & 31;
    if (warp >= B) return;
    const int b = warp;

    // Warp-uniform loads (one sector each, L1 broadcast). addr -> gather is
    // the single exposed latency chain; op is independent and overlaps.
    int   a  = __ldg(addr + b);
    int   op = __ldg(outp + b);
    float v  = fabsf(__ldg(mem + b * M + a));

    // --- unsigned integer digit ladder (exact; v < 2^24) ----------------------
    unsigned u  = (unsigned)v;       // exact floor for v >= 0
    unsigned q1 = u  / 10u;
    unsigned q2 = q1 / 10u;
    unsigned q3 = q2 / 10u;
    unsigned q4 = q3 / 10u;
    unsigned q5 = q4 / 10u;
    unsigned q6 = q5 / 10u;

    unsigned d1 = (q1 <= 101u) ? (q1 - 10u * q2) : 0u;
    unsigned d2 = (q2 <= 11u)  ? (q2 - 10u * q3) : 0u;
    unsigned d3 = (q3 <= 2u)   ? (q3 - 10u * q4) : 0u;
    unsigned d4 = (q4 <= 1u)   ? q4 : 0u;   // q4<=1 => digit == q4
    unsigned d5 = (q5 <= 1u)   ? q5 : 0u;

    // digit count from the ladder: q_p != 0  <=>  u >= 10^p
    int n = 1 + (q1 != 0u) + (q2 != 0u) + (q3 != 0u)
              + (q4 != 0u) + (q5 != 0u);

    // --- qmax cutoff bands (warp-uniform branch, ~0.03% taken) ----------------
    if (v > 1018.0f && v < 20001.0f) {
        if (fabsf(v - 1019.5f) < 1.41f) {
            float g = 1019.5f - v;
            float s = (g > -1.4011f) ? st_fast(g) : 0.0f;
            d1 = (unsigned)mod10_digit(101.0f * s);
        } else if (fabsf(v - 1199.5f) < 1.41f) {
            float g = 1199.5f - v;
            float s = (g > -1.4011f) ? st_fast(g) : 0.0f;
            d2 = (unsigned)mod10_digit(11.0f * s);
        } else if (fabsf(v - 2999.5f) < 1.41f) {
            float g = 2999.5f - v;
            float s = (g > -1.4011f) ? st_fast(g) : 0.0f;
            d3 = (unsigned)mod10_digit(2.0f * s);
        } else if (fabsf(v - 19999.5f) < 1.41f) {
            float g = 19999.5f - v;
            float s = (g > -1.4011f) ? st_fast(g) : 0.0f;
            d4 = (unsigned)mod10_digit(1.0f * s);
        }
    }

    // --- pos 0: soft 4-term ascending sum (warp-uniform, ~1% taken) -----------
    unsigned d0 = 0u;
    if (v < 1001.0f) {
        const unsigned FULL = 0xFFFFFFFFu;
        int off = lane & 3;                        // each 4-lane group computes
        int qlo = (int)floorf(v - 1.93f) + 1;      // the same 4 live terms
        int q = qlo + off;
        float term = 0.0f;
        if (q >= 0 && q <= 999) {
            float qf = (float)q;
            float a1 = v - qf + 0.5f;              // lower gate arg (d = 1)
            float a2 = qf + 0.5f - v;              // upper gate arg
            term = st_fast(a1) * st_fast(a2) * qf;
        }
        term += __shfl_xor_sync(FULL, term, 1);    // group-of-4 reduction
        term += __shfl_xor_sync(FULL, term, 2);
        d0 = (unsigned)mod10_digit(term);
    }

    // --- nibble-pack digits (warp-uniform) -------------------------------------
    unsigned pack = d0 | (d1 << 4) | (d2 << 8)
                  | (d3 << 12) | (d4 << 16) | (d5 << 20);

    // --- branch-free epilogue: lane owns cols lane and lane+32 ------------------
    float* orow = out + b * 65;
    int j0 = lane - op;
    int j1 = j0 + 32;

    int pi0 = n - 1 - j0; pi0 = pi0 < 0 ? 0 : (pi0 > 5 ? 5 : pi0);
    int pi1 = n - 1 - j1; pi1 = pi1 < 0 ? 0 : (pi1 > 5 ? 5 : pi1);
    float g0 = (float)((pack >> (pi0 * 4)) & 15u);
    float g1 = (float)((pack >> (pi1 * 4)) & 15u);

    float t0 = (j0 >= 0 && j0 < n) ? (48.0f + g0) : ((j0 == n) ? 10.0f : 0.0f);
    float t1 = (j1 >= 0 && j1 < n) ? (48.0f + g1) : ((j1 == n) ? 10.0f : 0.0f);

    orow[lane]      = t0;        // two coalesced 128B stores per row
    orow[lane + 32] = t1;
    if (lane == 0) orow[64] = v; // appended value column (exact)
}

extern "C" void kernel_launch(void* const* d_in, const int* in_sizes, int n_in,
                              void* d_out, int out_size) {
    const float* mem  = (const float*)d_in[0];   // [B, M] fp32
    const int*   addr = (const int*)d_in[1];     // [B] int32
    const int*   outp = (const int*)d_in[2];     // [B] int32
    float*       out  = (float*)d_out;           // [B, 65] fp32

    int B = in_sizes[1];
    int M = in_sizes[0] / B;

    // Best-measured config: warp-per-row, 8 warps/block, 1024 blocks.
    int threads = 256;
    int blocks  = (B + (threads / 32) - 1) / (threads / 32);
    c4_printf_warp_kernel<<<blocks, threads>>>(mem, addr, outp, out, B, M);
}

// round 11
// speedup vs baseline: 1.1884x; 1.0048x over previous
#include <cuda_runtime.h>

// ---------------------------------------------------------------------------
// R11: 2 rows per warp + epilogue short-circuit.
//
// Floor decomposition (R6-R10): elapsed = launch/distribution overhead
// (~5000 cyc, invariant) + gather-chain exposure + issue term. R10 proved the
// issue term still partially binds (inst squeeze gave -7.5%). This round
// halves total issued instructions without R8's occupancy collapse:
//  * lanes 0..1 own one row each -> ladder/count/pack run once per warp for
//    2 rows (SIMD); 4096 warps (~28/SM) still hide the gather latency.
//  * epilogue per row: token logic for the upper/lower 32-column half is
//    emitted only when op makes that half reachable (tokens live at
//    j <= n <= 6), removing dead select chains per row.
//
// Reference semantics (verified R2-R10, rel_err 3.279e-6):
//  * value = |mem[b, addr[b]]| exactly (eq_gate is an exact one-hot).
//  * floor(v/10^p) == unsigned /10 ladder on u = (unsigned)v  (v < 2^24).
//  * n = 1 + #{p in 1..5 : q_p != 0}.
//  * qmax clipping per pos {999,101,11,2,1,1} (reference loop break).
//  * cutoff bands (quot = qmax*st near v = (qmax+1)*d - 0.5): soft fallback.
//  * pos 0 soft 4-term ascending sum when v < 1001: soft fallback.
// ---------------------------------------------------------------------------

static __device__ __forceinline__ float sigm(float z) {
    return __fdividef(1.0f, 1.0f + __expf(-z));
}
// silu_threshold(x) = (silu(20x+10) - silu(20x-10)) / 20
static __device__ __forceinline__ float st_fast(float x) {
    float z1 = __fmaf_rn(20.0f, x, 10.0f);
    float z2 = __fmaf_rn(20.0f, x, -10.0f);
    return (z1 * sigm(z1) - z2 * sigm(z2)) * 0.05f;
}
// reference digit = floor(quot - floor(quot/10)*10); handles negative quot.
static __device__ __forceinline__ int mod10_digit(float quot) {
    return (int)floorf(quot - floorf(quot * 0.1f) * 10.0f);
}

// token for output column 'col' of a row with state (pk|n<<24, op):
// j = col - op; digit token for j < n, newline for j == n, else 0.
static __device__ __forceinline__ float token_at(int j, int n, unsigned pk) {
    int pi = n - 1 - j;
    pi = pi < 0 ? 0 : (pi > 5 ? 5 : pi);
    float g = (float)((pk >> (pi * 4)) & 15u);
    return (j >= 0 && j < n) ? (48.0f + g) : ((j == n) ? 10.0f : 0.0f);
}

__global__ void __launch_bounds__(256)
c4_printf_2r_kernel(const float* __restrict__ mem,
                    const int*   __restrict__ addr,
                    const int*   __restrict__ outp,
                    float*       __restrict__ out,
                    int B, int M) {
    const unsigned FULL = 0xFFFFFFFFu;
    int lane = threadIdx.x & 31;
    int warp = (blockIdx.x * blockDim.x + threadIdx.x) >> 5;
    int base = warp * 2;                 // rows base, base+1
    if (base >= B) return;

    // --- owner phase: lanes 0..1 each own one row ------------------------------
    int  myrow = base + lane;
    bool owner = (lane < 2) && (myrow < B);

    float    v   = 0.0f;
    int      op  = 0;
    unsigned pkn = 0;                    // nibble digits | (n << 24)

    if (owner) {
        int a = __ldg(addr + myrow);
        op    = __ldg(outp + myrow);
        v     = fabsf(__ldg(mem + myrow * M + a));   // MLP=2 in one LDG

        // unsigned integer digit ladder (exact; v < 2^24)
        unsigned u  = (unsigned)v;
        unsigned q1 = u  / 10u;
        unsigned q2 = q1 / 10u;
        unsigned q3 = q2 / 10u;
        unsigned q4 = q3 / 10u;
        unsigned q5 = q4 / 10u;

        unsigned d1 = (q1 <= 101u) ? (q1 - 10u * q2) : 0u;
        unsigned d2 = (q2 <= 11u)  ? (q2 - 10u * q3) : 0u;
        unsigned d3 = (q3 <= 2u)   ? (q3 - 10u * q4) : 0u;
        unsigned d4 = (q4 <= 1u)   ? q4 : 0u;
        unsigned d5 = (q5 <= 1u)   ? q5 : 0u;

        int n = 1 + (q1 != 0u) + (q2 != 0u) + (q3 != 0u)
                  + (q4 != 0u) + (q5 != 0u);

        // qmax cutoff bands (~0.03% of rows)
        if (v > 1018.0f && v < 20001.0f) {
            if (fabsf(v - 1019.5f) < 1.41f) {
                float g = 1019.5f - v;
                float s = (g > -1.4011f) ? st_fast(g) : 0.0f;
                d1 = (unsigned)mod10_digit(101.0f * s);
            } else if (fabsf(v - 1199.5f) < 1.41f) {
                float g = 1199.5f - v;
                float s = (g > -1.4011f) ? st_fast(g) : 0.0f;
                d2 = (unsigned)mod10_digit(11.0f * s);
            } else if (fabsf(v - 2999.5f) < 1.41f) {
                float g = 2999.5f - v;
                float s = (g > -1.4011f) ? st_fast(g) : 0.0f;
                d3 = (unsigned)mod10_digit(2.0f * s);
            } else if (fabsf(v - 19999.5f) < 1.41f) {
                float g = 19999.5f - v;
                float s = (g > -1.4011f) ? st_fast(g) : 0.0f;
                d4 = (unsigned)mod10_digit(1.0f * s);
            }
        }

        // pos 0: soft 4-term ascending sum (per-lane serial; ~1% of rows)
        unsigned d0 = 0u;
        if (v < 1001.0f) {
            int qlo = (int)floorf(v - 1.93f) + 1;
            float quot = 0.0f;
            #pragma unroll
            for (int k = 0; k < 4; ++k) {
                int q = qlo + k;
                if (q >= 0 && q <= 999) {
                    float qf = (float)q;
                    float a1 = v - qf + 0.5f;        // lower gate arg (d = 1)
                    float a2 = qf + 0.5f - v;        // upper gate arg
                    quot += st_fast(a1) * st_fast(a2) * qf;
                }
            }
            d0 = (unsigned)mod10_digit(quot);
        }

        pkn = d0 | (d1 << 4) | (d2 << 8) | (d3 << 12)
            | (d4 << 16) | (d5 << 20) | ((unsigned)n << 24);
    }

    // --- epilogue: 2 rows, 2 coalesced 128B stores each --------------------------
    #pragma unroll
    for (int r = 0; r < 2; ++r) {
        int row = base + r;
        if (row >= B) break;
        unsigned pk = __shfl_sync(FULL, pkn, r);
        int      o  = __shfl_sync(FULL, op,  r);
        float    vv = __shfl_sync(FULL, v,   r);
        int nn = (int)(pk >> 24);

        // tokens occupy columns o..o+n (n <= 6): each 32-col half is touched
        // only for a narrow op range — skip the dead half's select chain.
        float t0 = 0.0f, t1 = 0.0f;
        if (o <= 37)  t0 = token_at(lane - o, nn, pk);        // cols 0..31
        if (o >= 26)  t1 = token_at(lane + 32 - o, nn, pk);   // cols 32..63

        float* orow = out + row * 65;
        orow[lane]      = t0;
        orow[lane + 32] = t1;
        if (lane == 0) orow[64] = vv;    // appended value column (exact)
    }
}

extern "C" void kernel_launch(void* const* d_in, const int* in_sizes, int n_in,
                              void* d_out, int out_size) {
    const float* mem  = (const float*)d_in[0];   // [B, M] fp32
    const int*   addr = (const int*)d_in[1];     // [B] int32
    const int*   outp = (const int*)d_in[2];     // [B] int32
    float*       out  = (float*)d_out;           // [B, 65] fp32

    int B = in_sizes[1];
    int M = in_sizes[0] / B;

    // 2 rows per warp, 8 warps per block -> 16 rows per block, 512 blocks.
    int rows_per_block = 16;
    int blocks = (B + rows_per_block - 1) / rows_per_block;
    c4_printf_2r_kernel<<<blocks, 256>>>(mem, addr, outp, out, B, M);
}